// round 1
// baseline (speedup 1.0000x reference)
#include <cuda_runtime.h>
#include <float.h>
#include <stdint.h>

// ======================= scratch (device globals, no allocs) =======================
__device__ float g_h1[67108864];   // [2,128,64,64,64]
__device__ float g_h2[16777216];   // [2,256,32,32,32]
__device__ float g_h3[ 2097152];   // [2,256,16,16,16]
__device__ float g_q [ 2097152];   // quantized, same layout as g_h3
__device__ float g_r1[16777216];   // [2,256,32,32,32]
__device__ float g_r2[67108864];   // [2,128,64,64,64]
__device__ int   g_idx[32768];     // code index per flat row
__device__ float g_weff[8192];     // [128 ci][64 tap]  (dw3 folded with wo)
__device__ float g_bias_eff;
__device__ float g_partial[8192];  // per-block SSE partials

// ======================= conv3d stride2 k4 pad1 =======================
// out tile: 64 co x (2z x 8y x 8x = 128 sp) per block, 256 threads,
// each thread: 8 co x 4 sp accumulators.
template<int CIC, bool RELU>
__global__ void __launch_bounds__(256) conv_s2k4(
    const float* __restrict__ in, const float* __restrict__ w,
    const float* __restrict__ bias, float* __restrict__ out,
    int Ci, int Co, int Din, int Dout)
{
    extern __shared__ float sm[];
    float* sI = sm;                                   // [CIC][6][18][19]
    float* sW = sm + CIC * (6 * 18 * 19);             // [64][CIC][64]

    const int t  = threadIdx.x;
    const int b  = blockIdx.z;
    const int coBase = blockIdx.y * 64;

    const int nx = Dout >> 3, ny = Dout >> 3;
    int bx = blockIdx.x % nx;
    int tmp = blockIdx.x / nx;
    int by = tmp % ny;
    int bz = tmp / ny;
    const int Z0 = bz * 2, Y0 = by * 8, X0 = bx * 8;

    const int coG = t >> 5;          // 0..7
    const int spG = t & 31;
    const int z  = spG >> 4;         // 0..1
    const int y  = (spG >> 1) & 7;   // 0..7
    const int xg = spG & 1;          // x = xg*4 + i

    float acc[8][4];
#pragma unroll
    for (int j = 0; j < 8; j++)
#pragma unroll
        for (int i = 0; i < 4; i++) acc[j][i] = 0.f;

    const int gz0 = 2 * Z0 - 1, gy0 = 2 * Y0 - 1, gx0 = 2 * X0 - 1;
    const size_t DD = (size_t)Din * Din;

    for (int ciBase = 0; ciBase < Ci; ciBase += CIC) {
        __syncthreads();
        // input patch [CIC][6][18][18] (row stride 19 in smem)
        for (int e = t; e < CIC * 6 * 18 * 18; e += 256) {
            int lx = e % 18; int r = e / 18;
            int ly = r % 18; r /= 18;
            int lz = r % 6;  int ci = r / 6;
            int gz = gz0 + lz, gy = gy0 + ly, gx = gx0 + lx;
            float v = 0.f;
            if ((unsigned)gz < (unsigned)Din && (unsigned)gy < (unsigned)Din &&
                (unsigned)gx < (unsigned)Din)
                v = in[((size_t)(b * Ci + ciBase + ci)) * DD * Din +
                       (size_t)gz * DD + (size_t)gy * Din + gx];
            sI[((ci * 6 + lz) * 18 + ly) * 19 + lx] = v;
        }
        // weights [64co][CIC*64] contiguous copy per co
        for (int e = t; e < 64 * CIC * 64; e += 256) {
            int co = e / (CIC * 64); int r = e % (CIC * 64);
            sW[e] = w[((size_t)(coBase + co) * Ci + ciBase) * 64 + r];
        }
        __syncthreads();

        for (int ci = 0; ci < CIC; ci++) {
            const float* sIc = sI + ci * (6 * 18 * 19);
            const float* sWc = sW + (coG * 8) * (CIC * 64) + ci * 64;
            for (int kz = 0; kz < 4; kz++) {
                for (int ky = 0; ky < 4; ky++) {
                    const float* rowI = sIc + (2 * z + kz) * (18 * 19) +
                                        (2 * y + ky) * 19 + 8 * xg;
                    const float* wTap = sWc + kz * 16 + ky * 4;
#pragma unroll
                    for (int kx = 0; kx < 4; kx++) {
                        float iv0 = rowI[kx];
                        float iv1 = rowI[kx + 2];
                        float iv2 = rowI[kx + 4];
                        float iv3 = rowI[kx + 6];
#pragma unroll
                        for (int j = 0; j < 8; j++) {
                            float wv = wTap[j * (CIC * 64) + kx];
                            acc[j][0] += wv * iv0;
                            acc[j][1] += wv * iv1;
                            acc[j][2] += wv * iv2;
                            acc[j][3] += wv * iv3;
                        }
                    }
                }
            }
        }
    }

    const size_t OD = (size_t)Dout * Dout;
#pragma unroll
    for (int j = 0; j < 8; j++) {
        int co = coBase + coG * 8 + j;
        float bv = bias[co];
        size_t base = ((size_t)(b * Co + co)) * OD * Dout +
                      (size_t)(Z0 + z) * OD + (size_t)(Y0 + y) * Dout + X0 + xg * 4;
#pragma unroll
        for (int i = 0; i < 4; i++) {
            float v = acc[j][i] + bv;
            if (RELU) v = v > 0.f ? v : 0.f;
            out[base + i] = v;
        }
    }
}

// ======================= convTranspose3d stride2 k4 pad1 =======================
// out tile: 64 co x (2z x 8y x 8x = 128 out positions), each thread 8co x 4sp
// (4 x-positions of equal parity -> fixed 8-tap set per thread).
template<int CIC, bool RELU>
__global__ void __launch_bounds__(256) deconv_s2k4(
    const float* __restrict__ in, const float* __restrict__ dw,
    const float* __restrict__ bias, float* __restrict__ out,
    int Ci, int Co, int Din, int Dout)
{
    extern __shared__ float sm[];
    float* sI = sm;                         // [CIC][3][6][7]
    float* sW = sm + CIC * (3 * 6 * 7);     // [CIC][64co][64tap]

    const int t  = threadIdx.x;
    const int b  = blockIdx.z;
    const int coBase = blockIdx.y * 64;

    const int nx = Dout >> 3, ny = Dout >> 3;
    int bx = blockIdx.x % nx;
    int tmp = blockIdx.x / nx;
    int by = tmp % ny;
    int bz = tmp / ny;
    const int Z0 = bz * 2, Y0 = by * 8, X0 = bx * 8;

    const int coG = t >> 5;
    const int spG = t & 31;
    const int z  = spG >> 4;
    const int y  = (spG >> 1) & 7;
    const int xg = spG & 1;                 // x = xg + 2*i

    const int kz0 = (z + 1) & 1;
    const int ky0 = (y + 1) & 1;
    const int kx0 = (xg + 1) & 1;
    const int base_z = ((z  + 1 - kz0) >> 1) + 1;
    const int base_y = ((y  + 1 - ky0) >> 1) + 1;
    const int base_x = ((xg + 1 - kx0) >> 1) + 1;

    float acc[8][4];
#pragma unroll
    for (int j = 0; j < 8; j++)
#pragma unroll
        for (int i = 0; i < 4; i++) acc[j][i] = 0.f;

    const int iz0 = (Z0 >> 1) - 1, iy0 = (Y0 >> 1) - 1, ix0 = (X0 >> 1) - 1;
    const size_t DD = (size_t)Din * Din;

    for (int ciBase = 0; ciBase < Ci; ciBase += CIC) {
        __syncthreads();
        for (int e = t; e < CIC * 3 * 6 * 6; e += 256) {
            int lx = e % 6; int r = e / 6;
            int ly = r % 6; r /= 6;
            int lz = r % 3; int ci = r / 3;
            int gz = iz0 + lz, gy = iy0 + ly, gx = ix0 + lx;
            float v = 0.f;
            if ((unsigned)gz < (unsigned)Din && (unsigned)gy < (unsigned)Din &&
                (unsigned)gx < (unsigned)Din)
                v = in[((size_t)(b * Ci + ciBase + ci)) * DD * Din +
                       (size_t)gz * DD + (size_t)gy * Din + gx];
            sI[((ci * 3 + lz) * 6 + ly) * 7 + lx] = v;
        }
        for (int e = t; e < CIC * 4096; e += 256) {
            int ci = e >> 12; int r = e & 4095;
            sW[e] = dw[((size_t)(ciBase + ci) * Co + coBase) * 64 + r];
        }
        __syncthreads();

        for (int ci = 0; ci < CIC; ci++) {
            const float* sIc = sI + ci * (3 * 6 * 7);
            const float* sWc = sW + ci * 4096 + (coG * 8) * 64;
#pragma unroll
            for (int a = 0; a < 2; a++)
#pragma unroll
            for (int bb = 0; bb < 2; bb++)
#pragma unroll
            for (int c = 0; c < 2; c++) {
                int tap = (kz0 + 2 * a) * 16 + (ky0 + 2 * bb) * 4 + (kx0 + 2 * c);
                const float* rowI = sIc + (base_z - a) * 42 + (base_y - bb) * 7 +
                                    (base_x - c);
                float iv0 = rowI[0], iv1 = rowI[1], iv2 = rowI[2], iv3 = rowI[3];
#pragma unroll
                for (int j = 0; j < 8; j++) {
                    float wv = sWc[j * 64 + tap];
                    acc[j][0] += wv * iv0;
                    acc[j][1] += wv * iv1;
                    acc[j][2] += wv * iv2;
                    acc[j][3] += wv * iv3;
                }
            }
        }
    }

    const size_t OD = (size_t)Dout * Dout;
#pragma unroll
    for (int j = 0; j < 8; j++) {
        int co = coBase + coG * 8 + j;
        float bv = bias[co];
        size_t base = ((size_t)(b * Co + co)) * OD * Dout +
                      (size_t)(Z0 + z) * OD + (size_t)(Y0 + y) * Dout + X0 + xg;
#pragma unroll
        for (int i = 0; i < 4; i++) {
            float v = acc[j][i] + bv;
            if (RELU) v = v > 0.f ? v : 0.f;
            out[base + 2 * i] = v;
        }
    }
}

// ======================= fold dw3 & wo: weff[ci][tap] = sum_co dw3*wo =======================
__global__ void build_weff(const float* __restrict__ dw3, const float* __restrict__ db3,
                           const float* __restrict__ wo,  const float* __restrict__ bo)
{
    int t = blockIdx.x * 256 + threadIdx.x;
    if (t < 8192) {
        int ci = t >> 6, tap = t & 63;
        float s = 0.f;
        for (int co = 0; co < 128; co++)
            s += dw3[((size_t)(ci * 128 + co)) * 64 + tap] * wo[co];
        g_weff[t] = s;
    }
    if (t == 0) {
        float s = bo[0];
        for (int co = 0; co < 128; co++) s += db3[co] * wo[co];
        g_bias_eff = s;
    }
}

// ======================= fused deconv3 (Ci=128 -> 1 eff. out channel) =======================
// out tile 4z x 8y x 8x = 256, thread per output, writes final r to d_out+1.
__global__ void __launch_bounds__(256) fused_deconv3(float* __restrict__ out)
{
    __shared__ float sWe[8192];          // full weff
    __shared__ float sI[8 * 4 * 6 * 7];  // [8ci][4][6][7]

    const int t = threadIdx.x;
    const int b = blockIdx.z;
    int bx = blockIdx.x & 15;
    int by = (blockIdx.x >> 4) & 15;
    int bz = blockIdx.x >> 8;
    const int Z0 = bz * 4, Y0 = by * 8, X0 = bx * 8;

    const int z = t >> 6;
    const int y = (t >> 3) & 7;
    const int x = t & 7;

    for (int e = t; e < 8192; e += 256) sWe[e] = g_weff[e];

    const int kz0 = (z + 1) & 1, ky0 = (y + 1) & 1, kx0 = (x + 1) & 1;
    const int base_z = ((z + 1 - kz0) >> 1) + 1;
    const int base_y = ((y + 1 - ky0) >> 1) + 1;
    const int base_x = ((x + 1 - kx0) >> 1) + 1;

    const int iz0 = (Z0 >> 1) - 1, iy0 = (Y0 >> 1) - 1, ix0 = (X0 >> 1) - 1;

    float acc = 0.f;
    for (int ciBase = 0; ciBase < 128; ciBase += 8) {
        __syncthreads();
        for (int e = t; e < 8 * 4 * 6 * 6; e += 256) {
            int lx = e % 6; int r = e / 6;
            int ly = r % 6; r /= 6;
            int lz = r % 4; int ci = r / 4;
            int gz = iz0 + lz, gy = iy0 + ly, gx = ix0 + lx;
            float v = 0.f;
            if ((unsigned)gz < 64u && (unsigned)gy < 64u && (unsigned)gx < 64u)
                v = g_r2[((size_t)(b * 128 + ciBase + ci)) * 262144 +
                         (size_t)gz * 4096 + gy * 64 + gx];
            sI[((ci * 4 + lz) * 6 + ly) * 7 + lx] = v;
        }
        __syncthreads();

        for (int ci = 0; ci < 8; ci++) {
            const float* sIc = sI + ci * (4 * 6 * 7);
            const float* wc  = sWe + (ciBase + ci) * 64;
#pragma unroll
            for (int a = 0; a < 2; a++)
#pragma unroll
            for (int bb = 0; bb < 2; bb++)
#pragma unroll
            for (int c = 0; c < 2; c++) {
                int tap = (kz0 + 2 * a) * 16 + (ky0 + 2 * bb) * 4 + (kx0 + 2 * c);
                acc += sIc[(base_z - a) * 42 + (base_y - bb) * 7 + (base_x - c)] *
                       wc[tap];
            }
        }
    }

    out[(size_t)b * 2097152 + (size_t)(Z0 + z) * 16384 + (Y0 + y) * 128 + X0 + x] =
        acc + g_bias_eff;
}

// ======================= VQ argmin =======================
// 8 rows per block, one warp per row; codes scanned ascending, strict <, so
// first-minimum semantics match jnp.argmin.
__global__ void __launch_bounds__(256) vq_argmin(const float* __restrict__ h3,
                                                 const float* __restrict__ emb)
{
    __shared__ float sF[8][64];
    __shared__ float sE[64][65];

    const int t = threadIdx.x;
    const int r = t >> 5;
    const int tr = t & 31;
    const int n0 = blockIdx.x * 8;

    for (int e = t; e < 512; e += 256) {
        int rr = e >> 6, ee = e & 63;
        int n = n0 + rr;
        int p = n & 3; int v = n >> 2;
        int x = v & 15, y = (v >> 4) & 15, z = (v >> 8) & 15, b = v >> 12;
        sF[rr][ee] = h3[((size_t)(b * 256 + p * 64 + ee)) * 4096 +
                        z * 256 + y * 16 + x];
    }

    float best = FLT_MAX; int bidx = 0;
    for (int kc = 0; kc < 512; kc += 64) {
        __syncthreads();
        for (int e = t; e < 4096; e += 256)
            sE[e >> 6][e & 63] = emb[(size_t)(kc + (e >> 6)) * 64 + (e & 63)];
        __syncthreads();

        float d1 = 0.f, d2 = 0.f;
        for (int e = 0; e < 64; e++) {
            float f = sF[r][e];
            float a = f - sE[tr][e];
            float c = f - sE[tr + 32][e];
            d1 += a * a;
            d2 += c * c;
        }
        if (d1 < best) { best = d1; bidx = kc + tr; }
        if (d2 < best) { best = d2; bidx = kc + tr + 32; }
    }

    // warp reduce (prefer smaller index on ties)
    for (int off = 16; off; off >>= 1) {
        float od = __shfl_down_sync(0xffffffffu, best, off);
        int   oi = __shfl_down_sync(0xffffffffu, bidx, off);
        if (od < best || (od == best && oi < bidx)) { best = od; bidx = oi; }
    }
    if (tr == 0) g_idx[n0 + r] = bidx;
}

// ======================= quantize + SSE partials =======================
__global__ void __launch_bounds__(256) quant_loss(const float* __restrict__ h3,
                                                  const float* __restrict__ emb)
{
    __shared__ float sred[256];
    const int t = threadIdx.x;
    const int g = blockIdx.x * 256 + t;     // 0 .. 2097151
    int vox = g & 4095;
    int ch  = (g >> 12) & 255;
    int b   = g >> 20;
    int n   = ((b << 12) + vox) * 4 + (ch >> 6);
    float qv = emb[(size_t)g_idx[n] * 64 + (ch & 63)];
    float hv = h3[g];
    g_q[g] = qv;
    float d = qv - hv;
    sred[t] = d * d;
    __syncthreads();
    for (int s = 128; s; s >>= 1) {
        if (t < s) sred[t] += sred[t + s];
        __syncthreads();
    }
    if (t == 0) g_partial[blockIdx.x] = sred[0];
}

__global__ void __launch_bounds__(256) loss_final(float* __restrict__ out)
{
    __shared__ float sred[256];
    const int t = threadIdx.x;
    float s = 0.f;
    for (int k = 0; k < 32; k++) s += g_partial[t + 256 * k];
    sred[t] = s;
    __syncthreads();
    for (int st = 128; st; st >>= 1) {
        if (t < st) sred[t] += sred[t + st];
        __syncthreads();
    }
    if (t == 0) out[0] = sred[0] * 1.25f / 2097152.0f;
}

// ======================= launch =======================
extern "C" void kernel_launch(void* const* d_in, const int* in_sizes, int n_in,
                              void* d_out, int out_size)
{
    const float* x   = (const float*)d_in[0];
    const float* w1  = (const float*)d_in[1];
    const float* b1  = (const float*)d_in[2];
    const float* w2  = (const float*)d_in[3];
    const float* b2  = (const float*)d_in[4];
    const float* w3  = (const float*)d_in[5];
    const float* b3  = (const float*)d_in[6];
    const float* dw1 = (const float*)d_in[7];
    const float* db1 = (const float*)d_in[8];
    const float* dw2 = (const float*)d_in[9];
    const float* db2 = (const float*)d_in[10];
    const float* dw3 = (const float*)d_in[11];
    const float* db3 = (const float*)d_in[12];
    const float* wo  = (const float*)d_in[13];
    const float* bo  = (const float*)d_in[14];
    const float* emb = (const float*)d_in[15];
    float* out = (float*)d_out;

    float *h1, *h2, *h3, *q, *r1, *r2;
    cudaGetSymbolAddress((void**)&h1, g_h1);
    cudaGetSymbolAddress((void**)&h2, g_h2);
    cudaGetSymbolAddress((void**)&h3, g_h3);
    cudaGetSymbolAddress((void**)&q,  g_q);
    cudaGetSymbolAddress((void**)&r1, g_r1);
    cudaGetSymbolAddress((void**)&r2, g_r2);

    const int smem_c1 = (1 * (6 * 18 * 19) + 1 * 64 * 64) * 4;   // 24592
    const int smem_c2 = (2 * (6 * 18 * 19) + 2 * 64 * 64) * 4;   // 49184
    const int smem_dc = (4 * (3 * 6 * 7) + 4 * 64 * 64) * 4;     // 67552

    cudaFuncSetAttribute((const void*)conv_s2k4<1, true>,
                         cudaFuncAttributeMaxDynamicSharedMemorySize, smem_c1);
    cudaFuncSetAttribute((const void*)conv_s2k4<2, true>,
                         cudaFuncAttributeMaxDynamicSharedMemorySize, smem_c2);
    cudaFuncSetAttribute((const void*)conv_s2k4<2, false>,
                         cudaFuncAttributeMaxDynamicSharedMemorySize, smem_c2);
    cudaFuncSetAttribute((const void*)deconv_s2k4<4, true>,
                         cudaFuncAttributeMaxDynamicSharedMemorySize, smem_dc);

    // encoder
    conv_s2k4<1, true ><<<dim3(2048, 2, 2), 256, smem_c1>>>(x,  w1, b1, h1, 1,   128, 128, 64);
    conv_s2k4<2, true ><<<dim3(256,  4, 2), 256, smem_c2>>>(h1, w2, b2, h2, 128, 256, 64,  32);
    conv_s2k4<2, false><<<dim3(32,   4, 2), 256, smem_c2>>>(h2, w3, b3, h3, 256, 256, 32,  16);

    // VQ + loss
    vq_argmin<<<4096, 256>>>(h3, emb);
    quant_loss<<<8192, 256>>>(h3, emb);
    loss_final<<<1, 256>>>(out);

    // fold dw3/wo (cheap, overlappable)
    build_weff<<<32, 256>>>(dw3, db3, wo, bo);

    // decoder
    deconv_s2k4<4, true><<<dim3(256,  4, 2), 256, smem_dc>>>(q,  dw1, db1, r1, 256, 256, 16, 32);
    deconv_s2k4<4, true><<<dim3(2048, 2, 2), 256, smem_dc>>>(r1, dw2, db2, r2, 256, 128, 32, 64);

    // fused deconv3 + 1x1 conv -> final r
    fused_deconv3<<<dim3(8192, 1, 2), 256>>>(out + 1);
}